// round 13
// baseline (speedup 1.0000x reference)
#include <cuda_runtime.h>
#include <cuda_bf16.h>
#include <cstdint>
#include <cstddef>

// ---------------------------------------------------------------------------
// W8A8 Linear via legacy bf16 HMMA (mma.sync.m16n8k16.f32.bf16.bf16.f32).
//
// R12 analysis: co-bound on smem crossbar (~490us floor) and HMMA pipe
// (~454us floor). This round cuts smem bytes/MAC by 31%: warp tile 64x64,
// CTA tile 128x256 (8 warps, 2m x 4n), 1 CTA/SM, acc=128 regs/thread,
// 32 independent HMMAs per k-step for in-warp latency hiding.
//
//   out[m,n] = alpha * sum_k x[m,k]*w[n,k] + bias[n]
//
// Inputs arrive widened to 4-byte elements (established R6->R8); cvt kernels
// detect the encoding and emit packed bf16 scratch. Math exact.
// ---------------------------------------------------------------------------

static constexpr int K_TOTAL = 4096;
static constexpr int N_TOTAL = 4096;
static constexpr int M_MAX   = 8192;
static constexpr int BM = 128;
static constexpr int BN = 256;
static constexpr int BK_ELEM = 64;                   // bf16 elems per chunk
static constexpr int BKB = 128;                      // bytes per row per chunk
static constexpr int STAGES = 3;
static constexpr int K_CHUNKS = K_TOTAL / BK_ELEM;   // 64

static constexpr int A_BYTES = BM * BKB;                   // 16384
static constexpr int B_BYTES = BN * BKB;                   // 32768
static constexpr int STAGE_BYTES = A_BYTES + B_BYTES;      // 49152
static constexpr int SMEM_TOTAL = STAGES * STAGE_BYTES;    // 147456

static constexpr int NUM_THREADS = 256;

// ---------------------------------------------------------------------------
// Scratch (static device globals — no allocation)
// ---------------------------------------------------------------------------
__device__ __nv_bfloat16 g_xh[(size_t)M_MAX * K_TOTAL];    // 64 MB
__device__ __nv_bfloat16 g_wh[(size_t)N_TOTAL * K_TOTAL];  // 32 MB
__device__ int g_wide;                                     // 1 = 4B elements

// ---------------------------------------------------------------------------
// Input conversion
// ---------------------------------------------------------------------------

__device__ __forceinline__ float fix_elem(int v) {
    if ((unsigned)(v + 127) <= 254u) return (float)v;      // int32 encoding
    return __int_as_float(v);                              // float32 encoding
}

__global__ void detect_kernel(const int* __restrict__ probe) {
    const int lid = threadIdx.x & 31;
    int good = 0;
    for (int i = lid; i < 1024; i += 32) {
        const int v = probe[i];
        const float f = __int_as_float(v);
        const bool small_int = (unsigned)(v + 127) <= 254u;
        const bool small_flt = (f >= -127.5f && f <= 127.5f);
        if (small_int || small_flt) good++;
    }
    #pragma unroll
    for (int s = 16; s > 0; s >>= 1)
        good += __shfl_xor_sync(0xFFFFFFFFu, good, s);
    if (lid == 0) g_wide = (good >= 512) ? 1 : 0;
}

// Each thread emits 8 bf16 (16B). Wide: reads 8x4B. Narrow: reads 8x1B int8.
__global__ void cvt_bf16_kernel(const void* __restrict__ src, int sel, int n8) {
    const int i = blockIdx.x * blockDim.x + threadIdx.x;
    if (i >= n8) return;
    __nv_bfloat16* dst = sel ? g_wh : g_xh;
    float v[8];
    if (g_wide) {
        const int4* s = reinterpret_cast<const int4*>(src) + (size_t)i * 2;
        const int4 w0 = s[0];
        const int4 w1 = s[1];
        v[0] = fix_elem(w0.x); v[1] = fix_elem(w0.y);
        v[2] = fix_elem(w0.z); v[3] = fix_elem(w0.w);
        v[4] = fix_elem(w1.x); v[5] = fix_elem(w1.y);
        v[6] = fix_elem(w1.z); v[7] = fix_elem(w1.w);
    } else {
        const uint2 p = reinterpret_cast<const uint2*>(src)[i];
        #pragma unroll
        for (int j = 0; j < 4; j++)
            v[j] = (float)(int8_t)((p.x >> (8 * j)) & 0xFFu);
        #pragma unroll
        for (int j = 0; j < 4; j++)
            v[4 + j] = (float)(int8_t)((p.y >> (8 * j)) & 0xFFu);
    }
    uint4 o;
    uint16_t h[8];
    #pragma unroll
    for (int j = 0; j < 8; j++) {
        const __nv_bfloat16 b = __float2bfloat16_rn(v[j]);
        h[j] = *reinterpret_cast<const uint16_t*>(&b);
    }
    o.x = (uint32_t)h[0] | ((uint32_t)h[1] << 16);
    o.y = (uint32_t)h[2] | ((uint32_t)h[3] << 16);
    o.z = (uint32_t)h[4] | ((uint32_t)h[5] << 16);
    o.w = (uint32_t)h[6] | ((uint32_t)h[7] << 16);
    reinterpret_cast<uint4*>(dst)[i] = o;
}

// ---------------------------------------------------------------------------
// PTX helpers (baseline PTX only)
// ---------------------------------------------------------------------------

__device__ __forceinline__ uint32_t smem_u32(const void* p) {
    uint32_t a;
    asm("{ .reg .u64 t; cvta.to.shared.u64 t, %1; cvt.u32.u64 %0, t; }"
        : "=r"(a) : "l"(p));
    return a;
}

__device__ __forceinline__ void cp16(uint32_t dst_smem, const void* src_gmem) {
    asm volatile("cp.async.cg.shared.global [%0], [%1], 16;"
                 :: "r"(dst_smem), "l"(src_gmem));
}

__device__ __forceinline__ void cp_commit() {
    asm volatile("cp.async.commit_group;" ::: "memory");
}

template <int N>
__device__ __forceinline__ void cp_wait() {
    asm volatile("cp.async.wait_group %0;" :: "n"(N) : "memory");
}

__device__ __forceinline__ void ldsm_x4(uint32_t* r, uint32_t addr) {
    asm volatile("ldmatrix.sync.aligned.m8n8.x4.shared.b16 {%0,%1,%2,%3}, [%4];"
                 : "=r"(r[0]), "=r"(r[1]), "=r"(r[2]), "=r"(r[3]) : "r"(addr));
}

__device__ __forceinline__ void hmma16816(float* d, const uint32_t* a,
                                          const uint32_t* b) {
    asm volatile(
        "mma.sync.aligned.m16n8k16.row.col.f32.bf16.bf16.f32 "
        "{%0,%1,%2,%3}, {%4,%5,%6,%7}, {%8,%9}, {%0,%1,%2,%3};"
        : "+f"(d[0]), "+f"(d[1]), "+f"(d[2]), "+f"(d[3])
        : "r"(a[0]), "r"(a[1]), "r"(a[2]), "r"(a[3]), "r"(b[0]), "r"(b[1]));
}

// ---------------------------------------------------------------------------
// GEMM kernel.  SMEM swizzle: (row r, byte col cb) -> r*128 + (cb^((r&7)<<4)).
// ldmatrix lane->address maps exactly as verified in R11/R12 (bit-exact).
// Warp grid: warp_m = wid&1 (64-row slab), warp_n = wid>>1 (64-col slab).
// ---------------------------------------------------------------------------

__global__ void __launch_bounds__(NUM_THREADS, 1)
w8a8_hmma_kernel(float* __restrict__ out,
                 const float* __restrict__ bias,
                 const float* __restrict__ alpha_p)
{
    extern __shared__ char smem[];
    const uint32_t sb = smem_u32(smem);
    const int tid = threadIdx.x;
    const int wid = tid >> 5;
    const int lid = tid & 31;

    const int m_base = blockIdx.y * BM;
    const int n_base = blockIdx.x * BN;

    const int warp_m = wid & 1;    // 0..1 -> 64-row slab
    const int warp_n = wid >> 1;   // 0..3 -> 64-col slab

    // ---- producer precompute: 4 A units + 8 B units of 16B per thread -----
    uint32_t a_dst[4];
    const __nv_bfloat16* a_src[4];
    #pragma unroll
    for (int i = 0; i < 4; i++) {
        const int u = tid + i * 256;           // 0..1023 units (128 rows)
        const int r = u >> 3;
        const int cb = (u & 7) * 16;
        a_dst[i] = (uint32_t)(r * BKB + (cb ^ ((r & 7) << 4)));
        a_src[i] = g_xh + (size_t)(m_base + r) * K_TOTAL + cb / 2;
    }
    uint32_t b_dst[8];
    const __nv_bfloat16* b_src[8];
    #pragma unroll
    for (int i = 0; i < 8; i++) {
        const int u = tid + i * 256;           // 0..2047 units (256 rows)
        const int r = u >> 3;
        const int cb = (u & 7) * 16;
        b_dst[i] = (uint32_t)(r * BKB + (cb ^ ((r & 7) << 4)));
        b_src[i] = g_wh + (size_t)(n_base + r) * K_TOTAL + cb / 2;
    }

    // ---- ldmatrix lane address precompute (verified maps) -----------------
    const uint32_t lmask = (uint32_t)((lid & 7) << 4);              // swizzle
    const uint32_t a_k16 = (uint32_t)(lid & 16);                    // A koff
    const uint32_t b_k16 = (uint32_t)((lid & 8) << 1);              // B koff
    const uint32_t a_row16 = (uint32_t)(lid & 15);
    const uint32_t b_row16 = (uint32_t)((lid & 7) + ((lid & 16) >> 1));
    const uint32_t a_rb = (uint32_t)((warp_m * 64 + a_row16) * BKB);
    const uint32_t b_rb = (uint32_t)((warp_n * 64 + b_row16) * BKB);

    float acc[4][8][4];
    #pragma unroll
    for (int fm = 0; fm < 4; fm++)
        #pragma unroll
        for (int fn = 0; fn < 8; fn++)
            #pragma unroll
            for (int q = 0; q < 4; q++) acc[fm][fn][q] = 0.0f;

    // ---- prologue: fill stages 0..1 ---------------------------------------
    #pragma unroll
    for (int s = 0; s < STAGES - 1; s++) {
        const uint32_t sA = sb + s * STAGE_BYTES;
        const uint32_t sB = sA + A_BYTES;
        #pragma unroll
        for (int i = 0; i < 4; i++) cp16(sA + a_dst[i], a_src[i] + s * BK_ELEM);
        #pragma unroll
        for (int i = 0; i < 8; i++) cp16(sB + b_dst[i], b_src[i] + s * BK_ELEM);
        cp_commit();
    }

    // ---- main loop --------------------------------------------------------
    int stage = 0;
    #pragma unroll 1
    for (int kc = 0; kc < K_CHUNKS; kc++) {
        cp_wait<STAGES - 2>();
        __syncthreads();

        const int kn = kc + STAGES - 1;
        if (kn < K_CHUNKS) {
            int sn = stage + STAGES - 1;
            if (sn >= STAGES) sn -= STAGES;
            const uint32_t pA = sb + sn * STAGE_BYTES;
            const uint32_t pB = pA + A_BYTES;
            const int koff = kn * BK_ELEM;
            #pragma unroll
            for (int i = 0; i < 4; i++) cp16(pA + a_dst[i], a_src[i] + koff);
            #pragma unroll
            for (int i = 0; i < 8; i++) cp16(pB + b_dst[i], b_src[i] + koff);
        }
        cp_commit();

        const uint32_t sA = sb + stage * STAGE_BYTES;
        const uint32_t sB = sA + A_BYTES;
        if (++stage == STAGES) stage = 0;

        #pragma unroll
        for (int ks = 0; ks < 4; ks++) {          // 4 x k16 per 128B chunk
            const uint32_t kb = (uint32_t)(ks << 5);
            const uint32_t aoff = (kb | a_k16) ^ lmask;
            const uint32_t boff = (kb | b_k16) ^ lmask;

            uint32_t a[4][4];
            #pragma unroll
            for (int fm = 0; fm < 4; fm++)
                ldsm_x4(a[fm], sA + a_rb + (uint32_t)(fm * 16 * BKB) + aoff);

            uint32_t bf[4][4];   // bf[p] = {fn=2p:b0,b1, fn=2p+1:b0,b1}
            #pragma unroll
            for (int p = 0; p < 4; p++)
                ldsm_x4(bf[p], sB + b_rb + (uint32_t)(p * 16 * BKB) + boff);

            #pragma unroll
            for (int fm = 0; fm < 4; fm++)
                #pragma unroll
                for (int fn = 0; fn < 8; fn++)
                    hmma16816(acc[fm][fn], a[fm], &bf[fn >> 1][(fn & 1) * 2]);
        }
    }
    cp_wait<0>();

    // ---- epilogue: alpha * acc + bias -------------------------------------
    const float alpha = __ldg(alpha_p);
    const int g  = lid >> 2;
    const int tg = lid & 3;

    #pragma unroll
    for (int fm = 0; fm < 4; fm++) {
        const int row = m_base + warp_m * 64 + fm * 16 + g;
        float* o0 = out + (size_t)row * N_TOTAL;
        float* o1 = out + (size_t)(row + 8) * N_TOTAL;
        #pragma unroll
        for (int fn = 0; fn < 8; fn++) {
            const int col = n_base + warp_n * 64 + fn * 8 + tg * 2;
            const float b0 = __ldg(bias + col);
            const float b1 = __ldg(bias + col + 1);
            float2 v0, v1;
            v0.x = fmaf(alpha, acc[fm][fn][0], b0);
            v0.y = fmaf(alpha, acc[fm][fn][1], b1);
            v1.x = fmaf(alpha, acc[fm][fn][2], b0);
            v1.y = fmaf(alpha, acc[fm][fn][3], b1);
            *reinterpret_cast<float2*>(o0 + col) = v0;
            *reinterpret_cast<float2*>(o1 + col) = v1;
        }
    }
}

// ---------------------------------------------------------------------------
// Launch — inputs identified by element count; M from out_size.
// ---------------------------------------------------------------------------

extern "C" void kernel_launch(void* const* d_in, const int* in_sizes, int n_in,
                              void* d_out, int out_size)
{
    const void* px = nullptr;
    const void* pw = nullptr;
    const void* pb = nullptr;
    const void* pa = nullptr;

    for (int i = 0; i < n_in; i++) {
        const long s = (long)in_sizes[i];
        if (s == 1)                            pa = d_in[i];
        else if (s == (long)N_TOTAL)           pb = d_in[i];
        else if (s == (long)N_TOTAL * K_TOTAL) pw = d_in[i];
        else                                   px = d_in[i];
    }
    if (!px || !pw || !pb || !pa) {   // fallback: declared order
        px = d_in[0]; pw = d_in[1]; pb = d_in[2]; pa = d_in[3];
    }

    const int M = out_size / N_TOTAL;            // 8192
    const int nx8 = (M * K_TOTAL) / 8;
    const int nw8 = (N_TOTAL * K_TOTAL) / 8;

    detect_kernel<<<1, 32>>>((const int*)px);
    cvt_bf16_kernel<<<(nx8 + 255) / 256, 256>>>(px, 0, nx8);
    cvt_bf16_kernel<<<(nw8 + 255) / 256, 256>>>(pw, 1, nw8);

    cudaFuncSetAttribute(w8a8_hmma_kernel,
                         cudaFuncAttributeMaxDynamicSharedMemorySize, SMEM_TOTAL);

    dim3 grid(N_TOTAL / BN, M / BM);   // (16, 64)
    w8a8_hmma_kernel<<<grid, NUM_THREADS, SMEM_TOTAL>>>(
        (float*)d_out, (const float*)pb, (const float*)pa);
}

// round 15
// speedup vs baseline: 1.0432x; 1.0432x over previous
#include <cuda_runtime.h>
#include <cuda_bf16.h>
#include <cstdint>
#include <cstddef>

// ---------------------------------------------------------------------------
// W8A8 Linear via legacy bf16 HMMA (mma.sync.m16n8k16.f32.bf16.bf16.f32).
//
// R13 post-mortem: warps/SMSP (not in-warp ILP) hides latency here; 64x32
// warp tile @ 16 warps/SM is the RF-optimal point (R11, tensor 75.2%).
// This round: ONE 512-thread CTA (16 warps, 4m x 4n), CTA tile 256x128,
// 4-stage cp.async pipeline (192KB smem), halved A-side L2 traffic,
// merged cvt pre-pass. Verified swizzle/ldmatrix maps unchanged.
//
//   out[m,n] = alpha * sum_k x[m,k]*w[n,k] + bias[n]
// ---------------------------------------------------------------------------

static constexpr int K_TOTAL = 4096;
static constexpr int N_TOTAL = 4096;
static constexpr int M_MAX   = 8192;
static constexpr int BM = 256;
static constexpr int BN = 128;
static constexpr int BK_ELEM = 64;                   // bf16 elems per chunk
static constexpr int BKB = 128;                      // bytes per row per chunk
static constexpr int STAGES = 4;
static constexpr int K_CHUNKS = K_TOTAL / BK_ELEM;   // 64

static constexpr int A_BYTES = BM * BKB;                   // 32768
static constexpr int B_BYTES = BN * BKB;                   // 16384
static constexpr int STAGE_BYTES = A_BYTES + B_BYTES;      // 49152
static constexpr int SMEM_TOTAL = STAGES * STAGE_BYTES;    // 196608

static constexpr int NUM_THREADS = 512;

// ---------------------------------------------------------------------------
// Scratch (static device globals — no allocation)
// ---------------------------------------------------------------------------
__device__ __nv_bfloat16 g_xh[(size_t)M_MAX * K_TOTAL];    // 64 MB
__device__ __nv_bfloat16 g_wh[(size_t)N_TOTAL * K_TOTAL];  // 32 MB
__device__ int g_wide;                                     // 1 = 4B elements

// ---------------------------------------------------------------------------
// Input conversion
// ---------------------------------------------------------------------------

__device__ __forceinline__ float fix_elem(int v) {
    if ((unsigned)(v + 127) <= 254u) return (float)v;      // int32 encoding
    return __int_as_float(v);                              // float32 encoding
}

__global__ void detect_kernel(const int* __restrict__ probe) {
    const int lid = threadIdx.x & 31;
    int good = 0;
    for (int i = lid; i < 1024; i += 32) {
        const int v = probe[i];
        const float f = __int_as_float(v);
        const bool small_int = (unsigned)(v + 127) <= 254u;
        const bool small_flt = (f >= -127.5f && f <= 127.5f);
        if (small_int || small_flt) good++;
    }
    #pragma unroll
    for (int s = 16; s > 0; s >>= 1)
        good += __shfl_xor_sync(0xFFFFFFFFu, good, s);
    if (lid == 0) g_wide = (good >= 512) ? 1 : 0;
}

// Single merged conversion: indices [0, nx8) -> x, [nx8, nx8+nw8) -> w.
__global__ void cvt_bf16_kernel(const void* __restrict__ xsrc,
                                const void* __restrict__ wsrc,
                                int nx8, int ntot8) {
    int i = blockIdx.x * blockDim.x + threadIdx.x;
    if (i >= ntot8) return;
    const void* src;
    __nv_bfloat16* dst;
    if (i < nx8) { src = xsrc; dst = g_xh; }
    else         { src = wsrc; dst = g_wh; i -= nx8; }

    float v[8];
    if (g_wide) {
        const int4* s = reinterpret_cast<const int4*>(src) + (size_t)i * 2;
        const int4 w0 = s[0];
        const int4 w1 = s[1];
        v[0] = fix_elem(w0.x); v[1] = fix_elem(w0.y);
        v[2] = fix_elem(w0.z); v[3] = fix_elem(w0.w);
        v[4] = fix_elem(w1.x); v[5] = fix_elem(w1.y);
        v[6] = fix_elem(w1.z); v[7] = fix_elem(w1.w);
    } else {
        const uint2 p = reinterpret_cast<const uint2*>(src)[i];
        #pragma unroll
        for (int j = 0; j < 4; j++)
            v[j] = (float)(int8_t)((p.x >> (8 * j)) & 0xFFu);
        #pragma unroll
        for (int j = 0; j < 4; j++)
            v[4 + j] = (float)(int8_t)((p.y >> (8 * j)) & 0xFFu);
    }
    uint4 o;
    uint16_t h[8];
    #pragma unroll
    for (int j = 0; j < 8; j++) {
        const __nv_bfloat16 b = __float2bfloat16_rn(v[j]);
        h[j] = *reinterpret_cast<const uint16_t*>(&b);
    }
    o.x = (uint32_t)h[0] | ((uint32_t)h[1] << 16);
    o.y = (uint32_t)h[2] | ((uint32_t)h[3] << 16);
    o.z = (uint32_t)h[4] | ((uint32_t)h[5] << 16);
    o.w = (uint32_t)h[6] | ((uint32_t)h[7] << 16);
    reinterpret_cast<uint4*>(dst)[i] = o;
}

// ---------------------------------------------------------------------------
// PTX helpers (baseline PTX only)
// ---------------------------------------------------------------------------

__device__ __forceinline__ uint32_t smem_u32(const void* p) {
    uint32_t a;
    asm("{ .reg .u64 t; cvta.to.shared.u64 t, %1; cvt.u32.u64 %0, t; }"
        : "=r"(a) : "l"(p));
    return a;
}

__device__ __forceinline__ void cp16(uint32_t dst_smem, const void* src_gmem) {
    asm volatile("cp.async.cg.shared.global [%0], [%1], 16;"
                 :: "r"(dst_smem), "l"(src_gmem));
}

__device__ __forceinline__ void cp_commit() {
    asm volatile("cp.async.commit_group;" ::: "memory");
}

template <int N>
__device__ __forceinline__ void cp_wait() {
    asm volatile("cp.async.wait_group %0;" :: "n"(N) : "memory");
}

__device__ __forceinline__ void ldsm_x4(uint32_t* r, uint32_t addr) {
    asm volatile("ldmatrix.sync.aligned.m8n8.x4.shared.b16 {%0,%1,%2,%3}, [%4];"
                 : "=r"(r[0]), "=r"(r[1]), "=r"(r[2]), "=r"(r[3]) : "r"(addr));
}

__device__ __forceinline__ void hmma16816(float* d, const uint32_t* a,
                                          const uint32_t* b) {
    asm volatile(
        "mma.sync.aligned.m16n8k16.row.col.f32.bf16.bf16.f32 "
        "{%0,%1,%2,%3}, {%4,%5,%6,%7}, {%8,%9}, {%0,%1,%2,%3};"
        : "+f"(d[0]), "+f"(d[1]), "+f"(d[2]), "+f"(d[3])
        : "r"(a[0]), "r"(a[1]), "r"(a[2]), "r"(a[3]), "r"(b[0]), "r"(b[1]));
}

// ---------------------------------------------------------------------------
// GEMM kernel.  SMEM swizzle: (row r, byte col cb) -> r*128 + (cb^((r&7)<<4)).
// ldmatrix lane->address maps exactly as verified in R11/R12 (bit-exact).
// Warp grid: warp_m = wid&3 (64-row slab), warp_n = wid>>2 (32-col slab).
// ---------------------------------------------------------------------------

__global__ void __launch_bounds__(NUM_THREADS, 1)
w8a8_hmma_kernel(float* __restrict__ out,
                 const float* __restrict__ bias,
                 const float* __restrict__ alpha_p)
{
    extern __shared__ char smem[];
    const uint32_t sb = smem_u32(smem);
    const int tid = threadIdx.x;
    const int wid = tid >> 5;
    const int lid = tid & 31;

    const int m_base = blockIdx.y * BM;
    const int n_base = blockIdx.x * BN;

    const int warp_m = wid & 3;    // 0..3 -> 64-row slab
    const int warp_n = wid >> 2;   // 0..3 -> 32-col slab

    // ---- producer precompute: 4 A units + 2 B units of 16B per thread -----
    uint32_t a_dst[4];
    const __nv_bfloat16* a_src[4];
    #pragma unroll
    for (int i = 0; i < 4; i++) {
        const int u = tid + i * NUM_THREADS;   // 0..2047 units (256 rows)
        const int r = u >> 3;
        const int cb = (u & 7) * 16;
        a_dst[i] = (uint32_t)(r * BKB + (cb ^ ((r & 7) << 4)));
        a_src[i] = g_xh + (size_t)(m_base + r) * K_TOTAL + cb / 2;
    }
    uint32_t b_dst[2];
    const __nv_bfloat16* b_src[2];
    #pragma unroll
    for (int i = 0; i < 2; i++) {
        const int u = tid + i * NUM_THREADS;   // 0..1023 units (128 rows)
        const int r = u >> 3;
        const int cb = (u & 7) * 16;
        b_dst[i] = (uint32_t)(r * BKB + (cb ^ ((r & 7) << 4)));
        b_src[i] = g_wh + (size_t)(n_base + r) * K_TOTAL + cb / 2;
    }

    // ---- ldmatrix lane address precompute (verified maps) -----------------
    const uint32_t lmask = (uint32_t)((lid & 7) << 4);              // swizzle
    const uint32_t a_k16 = (uint32_t)(lid & 16);                    // A koff
    const uint32_t b_k16 = (uint32_t)((lid & 8) << 1);              // B koff
    const uint32_t a_row16 = (uint32_t)(lid & 15);
    const uint32_t b_row16 = (uint32_t)((lid & 7) + ((lid & 16) >> 1));
    const uint32_t a_rb = (uint32_t)((warp_m * 64 + a_row16) * BKB);
    const uint32_t b_rb = (uint32_t)((warp_n * 32 + b_row16) * BKB);

    float acc[4][4][4];
    #pragma unroll
    for (int fm = 0; fm < 4; fm++)
        #pragma unroll
        for (int fn = 0; fn < 4; fn++)
            #pragma unroll
            for (int q = 0; q < 4; q++) acc[fm][fn][q] = 0.0f;

    // ---- prologue: fill stages 0..2 ---------------------------------------
    #pragma unroll
    for (int s = 0; s < STAGES - 1; s++) {
        const uint32_t sA = sb + s * STAGE_BYTES;
        const uint32_t sB = sA + A_BYTES;
        #pragma unroll
        for (int i = 0; i < 4; i++) cp16(sA + a_dst[i], a_src[i] + s * BK_ELEM);
        #pragma unroll
        for (int i = 0; i < 2; i++) cp16(sB + b_dst[i], b_src[i] + s * BK_ELEM);
        cp_commit();
    }

    // ---- main loop --------------------------------------------------------
    int stage = 0;
    #pragma unroll 1
    for (int kc = 0; kc < K_CHUNKS; kc++) {
        cp_wait<STAGES - 2>();
        __syncthreads();

        const int kn = kc + STAGES - 1;
        if (kn < K_CHUNKS) {
            int sn = stage + STAGES - 1;
            if (sn >= STAGES) sn -= STAGES;
            const uint32_t pA = sb + sn * STAGE_BYTES;
            const uint32_t pB = pA + A_BYTES;
            const int koff = kn * BK_ELEM;
            #pragma unroll
            for (int i = 0; i < 4; i++) cp16(pA + a_dst[i], a_src[i] + koff);
            #pragma unroll
            for (int i = 0; i < 2; i++) cp16(pB + b_dst[i], b_src[i] + koff);
        }
        cp_commit();

        const uint32_t sA = sb + stage * STAGE_BYTES;
        const uint32_t sB = sA + A_BYTES;
        if (++stage == STAGES) stage = 0;

        #pragma unroll
        for (int ks = 0; ks < 4; ks++) {          // 4 x k16 per 128B chunk
            const uint32_t kb = (uint32_t)(ks << 5);
            const uint32_t aoff = (kb | a_k16) ^ lmask;
            const uint32_t boff = (kb | b_k16) ^ lmask;

            uint32_t a[4][4];
            #pragma unroll
            for (int fm = 0; fm < 4; fm++)
                ldsm_x4(a[fm], sA + a_rb + (uint32_t)(fm * 16 * BKB) + aoff);

            uint32_t bf[2][4];   // bf[p] = {fn=2p:b0,b1, fn=2p+1:b0,b1}
            #pragma unroll
            for (int p = 0; p < 2; p++)
                ldsm_x4(bf[p], sB + b_rb + (uint32_t)(p * 16 * BKB) + boff);

            #pragma unroll
            for (int fm = 0; fm < 4; fm++)
                #pragma unroll
                for (int fn = 0; fn < 4; fn++)
                    hmma16816(acc[fm][fn], a[fm], &bf[fn >> 1][(fn & 1) * 2]);
        }
    }
    cp_wait<0>();

    // ---- epilogue: alpha * acc + bias -------------------------------------
    const float alpha = __ldg(alpha_p);
    const int g  = lid >> 2;
    const int tg = lid & 3;

    #pragma unroll
    for (int fm = 0; fm < 4; fm++) {
        const int row = m_base + warp_m * 64 + fm * 16 + g;
        float* o0 = out + (size_t)row * N_TOTAL;
        float* o1 = out + (size_t)(row + 8) * N_TOTAL;
        #pragma unroll
        for (int fn = 0; fn < 4; fn++) {
            const int col = n_base + warp_n * 32 + fn * 8 + tg * 2;
            const float b0 = __ldg(bias + col);
            const float b1 = __ldg(bias + col + 1);
            float2 v0, v1;
            v0.x = fmaf(alpha, acc[fm][fn][0], b0);
            v0.y = fmaf(alpha, acc[fm][fn][1], b1);
            v1.x = fmaf(alpha, acc[fm][fn][2], b0);
            v1.y = fmaf(alpha, acc[fm][fn][3], b1);
            *reinterpret_cast<float2*>(o0 + col) = v0;
            *reinterpret_cast<float2*>(o1 + col) = v1;
        }
    }
}

// ---------------------------------------------------------------------------
// Launch — inputs identified by element count; M from out_size.
// ---------------------------------------------------------------------------

extern "C" void kernel_launch(void* const* d_in, const int* in_sizes, int n_in,
                              void* d_out, int out_size)
{
    const void* px = nullptr;
    const void* pw = nullptr;
    const void* pb = nullptr;
    const void* pa = nullptr;

    for (int i = 0; i < n_in; i++) {
        const long s = (long)in_sizes[i];
        if (s == 1)                            pa = d_in[i];
        else if (s == (long)N_TOTAL)           pb = d_in[i];
        else if (s == (long)N_TOTAL * K_TOTAL) pw = d_in[i];
        else                                   px = d_in[i];
    }
    if (!px || !pw || !pb || !pa) {   // fallback: declared order
        px = d_in[0]; pw = d_in[1]; pb = d_in[2]; pa = d_in[3];
    }

    const int M = out_size / N_TOTAL;            // 8192
    const int nx8 = (M * K_TOTAL) / 8;
    const int nw8 = (N_TOTAL * K_TOTAL) / 8;
    const int nt8 = nx8 + nw8;

    detect_kernel<<<1, 32>>>((const int*)px);
    cvt_bf16_kernel<<<(nt8 + 255) / 256, 256>>>(px, pw, nx8, nt8);

    cudaFuncSetAttribute(w8a8_hmma_kernel,
                         cudaFuncAttributeMaxDynamicSharedMemorySize, SMEM_TOTAL);

    dim3 grid(N_TOTAL / BN, M / BM);   // (32, 32)
    w8a8_hmma_kernel<<<grid, NUM_THREADS, SMEM_TOTAL>>>(
        (float*)d_out, (const float*)pb, (const float*)pa);
}